// round 11
// baseline (speedup 1.0000x reference)
#include <cuda_runtime.h>
#include <cuda_bf16.h>

// PointLayerNorm, R11: R10 + (a) zero kernel folded into finalize (stats are
// zeroed after being read, so each replay starts clean; first call relies on
// static zero-init), (b) norm manually unrolled x2 for doubled load MLP.

#define Bc 4
#define Nc 200000
#define Cc 96
#define C4 (Cc / 4)            // 24 float4 per point
#define Sc 32
#define KEYS (Bc * Sc)
#define EPSF 1e-5f
#define RGRID 592              // 148 SMs x 4 blocks: one wave

__device__ float g_sum[KEYS];    // static zero-init; re-zeroed by finalize
__device__ float g_sumsq[KEYS];
__device__ float4 g_sc[KEYS * C4];   // per (key, c4) scale
__device__ float4 g_sh[KEYS * C4];   // per (key, c4) shift

__device__ __forceinline__ void acc4(const float4 v, float& s, float& s2) {
    s += (v.x + v.y) + (v.z + v.w);
    s2 = fmaf(v.x, v.x, s2); s2 = fmaf(v.y, v.y, s2);
    s2 = fmaf(v.z, v.z, s2); s2 = fmaf(v.w, v.w, s2);
}

// Reduce: one warp owns a contiguous range of global points [g0, g1).
// Segment runs derived from the 33-entry offs array (batch_indices is
// non-decreasing) -> no idx loads, no shuffles/ballots in the hot loop.
__global__ __launch_bounds__(256) void pln_reduce_kernel(
    const float4* __restrict__ x4, const int* __restrict__ offs)
{
    const int P = Bc * Nc;
    int wid    = (blockIdx.x * blockDim.x + threadIdx.x) >> 5;
    int lane   = threadIdx.x & 31;
    int totalW = (RGRID * 256) >> 5;                         // 4736 warps
    int chunk  = (((P + totalW - 1) / totalW) + 15) & ~15;   // 176
    int g0 = wid * chunk;
    int g1 = min(g0 + chunk, P);
    if (g0 >= g1) return;

    int g = g0;
    while (g < g1) {
        int b = g / Nc;
        int n = g - b * Nc;
        int nlimit = min(Nc, n + (g1 - g));     // batch-local end of our range

        // binary search: largest seg with offs[seg] <= n  (offs[0]=0)
        int seg = 0;
        #pragma unroll
        for (int step = 16; step; step >>= 1) {
            int cand = seg + step;
            if (cand <= Sc - 1 && __ldg(&offs[cand]) <= n) seg = cand;
        }

        while (n < nlimit) {
            int rend = min(nlimit, __ldg(&offs[seg + 1]));
            int key  = b * Sc + seg;

            float sA = 0.f, sB = 0.f, s2A = 0.f, s2B = 0.f;
            const float4* base = x4 + ((size_t)b * Nc + n) * C4;

            // 16-point groups: 384 consecutive float4s, 12 LDG.128 per lane.
            for (; n + 16 <= rend; n += 16, base += 384) {
                float4 v0  = __ldg(base + lane);
                float4 v1  = __ldg(base + lane + 32);
                float4 v2  = __ldg(base + lane + 64);
                float4 v3  = __ldg(base + lane + 96);
                float4 v4  = __ldg(base + lane + 128);
                float4 v5  = __ldg(base + lane + 160);
                float4 v6  = __ldg(base + lane + 192);
                float4 v7  = __ldg(base + lane + 224);
                float4 v8  = __ldg(base + lane + 256);
                float4 v9  = __ldg(base + lane + 288);
                float4 v10 = __ldg(base + lane + 320);
                float4 v11 = __ldg(base + lane + 352);
                acc4(v0,  sA, s2A); acc4(v1,  sB, s2B);
                acc4(v2,  sA, s2A); acc4(v3,  sB, s2B);
                acc4(v4,  sA, s2A); acc4(v5,  sB, s2B);
                acc4(v6,  sA, s2A); acc4(v7,  sB, s2B);
                acc4(v8,  sA, s2A); acc4(v9,  sB, s2B);
                acc4(v10, sA, s2A); acc4(v11, sB, s2B);
            }
            // 8-point group (at most one)
            for (; n + 8 <= rend; n += 8, base += 192) {
                float4 v0 = __ldg(base + lane);
                float4 v1 = __ldg(base + lane + 32);
                float4 v2 = __ldg(base + lane + 64);
                float4 v3 = __ldg(base + lane + 96);
                float4 v4 = __ldg(base + lane + 128);
                float4 v5 = __ldg(base + lane + 160);
                acc4(v0, sA, s2A); acc4(v1, sB, s2B);
                acc4(v2, sA, s2A); acc4(v3, sB, s2B);
                acc4(v4, sA, s2A); acc4(v5, sB, s2B);
            }
            // remainder: single points, 24 active lanes
            for (; n < rend; ++n, base += 24) {
                if (lane < C4) {
                    float4 v = __ldg(base + lane);
                    acc4(v, sA, s2A);
                }
            }

            // flush this run
            float s = sA + sB, s2 = s2A + s2B;
            #pragma unroll
            for (int o = 16; o; o >>= 1) {
                s  += __shfl_xor_sync(0xffffffffu, s,  o);
                s2 += __shfl_xor_sync(0xffffffffu, s2, o);
            }
            if (lane == 0) {
                atomicAdd(&g_sum[key],   s);
                atomicAdd(&g_sumsq[key], s2);
            }
            if (n < nlimit) ++seg;   // next segment in this batch
        }
        g = b * Nc + nlimit;         // next batch-slice re-searches seg
    }
}

// Per-(key, c4) scale/shift tables, then zero the stats for the next replay.
__global__ void pln_finalize_kernel(const int* __restrict__ offs,
                                    const float4* __restrict__ w4,
                                    const float4* __restrict__ b4)
{
    int i = blockIdx.x * blockDim.x + threadIdx.x;
    if (i < KEYS * C4) {
        int k  = i / C4;
        int c4 = i - k * C4;
        int seg = k & (Sc - 1);
        float cnt = (float)(offs[seg + 1] - offs[seg]) * (float)Cc;
        float m   = g_sum[k] / cnt;
        float var = g_sumsq[k] / cnt - m * m;
        float iv  = rsqrtf(var + EPSF);
        float4 wv = __ldg(w4 + c4);
        float4 bv = __ldg(b4 + c4);
        float4 sc, sh;
        sc.x = iv * wv.x; sh.x = fmaf(-m, sc.x, bv.x);
        sc.y = iv * wv.y; sh.y = fmaf(-m, sc.y, bv.y);
        sc.z = iv * wv.z; sh.z = fmaf(-m, sc.z, bv.z);
        sc.w = iv * wv.w; sh.w = fmaf(-m, sc.w, bv.w);
        g_sc[i] = sc;
        g_sh[i] = sh;
        if (c4 == 0) {                // one thread per key zeroes its stats
            g_sum[k]   = 0.f;
            g_sumsq[k] = 0.f;
        }
    }
}

// Norm: division-free, c4 loop-invariant per thread; x2 manual unroll so two
// independent LDG.128 are in flight before either is consumed.
__global__ __launch_bounds__(256) void pln_norm_kernel(
    const float4* __restrict__ x4, const int* __restrict__ idx,
    float4* __restrict__ out4)
{
    const int P = Bc * Nc;
    const int E = P * C4;                      // 19,200,000 float4s
    int T   = gridDim.x * blockDim.x;          // multiple of 24 by launch config
    int tid = blockIdx.x * blockDim.x + threadIdx.x;
    int dp  = T / C4;

    int p  = tid / C4;
    int c4 = tid - p * C4;
    int b  = p / Nc;
    int n  = p - b * Nc;

    int e = tid;
    for (; e + T < E; e += 2 * T) {
        // element 0
        int key0 = (b * Sc + __ldg(&idx[n])) & (KEYS - 1);
        int n1i = n + dp, b1i = b;
        if (n1i >= Nc) { n1i -= Nc; ++b1i; }
        // element 1
        int key1 = (b1i * Sc + __ldg(&idx[n1i])) & (KEYS - 1);

        float4 xv0 = __ldcs(x4 + e);
        float4 xv1 = __ldcs(x4 + e + T);
        float4 sc0 = g_sc[key0 * C4 + c4];
        float4 sh0 = g_sh[key0 * C4 + c4];
        float4 sc1 = g_sc[key1 * C4 + c4];
        float4 sh1 = g_sh[key1 * C4 + c4];

        float4 o0, o1;
        o0.x = fmaf(xv0.x, sc0.x, sh0.x);
        o0.y = fmaf(xv0.y, sc0.y, sh0.y);
        o0.z = fmaf(xv0.z, sc0.z, sh0.z);
        o0.w = fmaf(xv0.w, sc0.w, sh0.w);
        o1.x = fmaf(xv1.x, sc1.x, sh1.x);
        o1.y = fmaf(xv1.y, sc1.y, sh1.y);
        o1.z = fmaf(xv1.z, sc1.z, sh1.z);
        o1.w = fmaf(xv1.w, sc1.w, sh1.w);
        __stcs(out4 + e,     o0);
        __stcs(out4 + e + T, o1);

        n = n1i + dp; b = b1i;
        if (n >= Nc) { n -= Nc; ++b; }
    }
    // tail (at most one element)
    for (; e < E; e += T) {
        int key = (b * Sc + __ldg(&idx[n])) & (KEYS - 1);
        int t   = key * C4 + c4;
        float4 sc = g_sc[t];
        float4 sh = g_sh[t];
        float4 xv = __ldcs(x4 + e);
        float4 o;
        o.x = fmaf(xv.x, sc.x, sh.x);
        o.y = fmaf(xv.y, sc.y, sh.y);
        o.z = fmaf(xv.z, sc.z, sh.z);
        o.w = fmaf(xv.w, sc.w, sh.w);
        __stcs(out4 + e, o);
        n += dp;
        if (n >= Nc) { n -= Nc; ++b; }
    }
}

extern "C" void kernel_launch(void* const* d_in, const int* in_sizes, int n_in,
                              void* d_out, int out_size) {
    const float4* x4   = (const float4*)d_in[0];
    const int*    offs = (const int*)d_in[1];
    const int*    idx  = (const int*)d_in[2];
    const float4* w4   = (const float4*)d_in[3];
    const float4* b4   = (const float4*)d_in[4];
    float4* out4 = (float4*)d_out;

    pln_reduce_kernel<<<RGRID, 256>>>(x4, offs);
    pln_finalize_kernel<<<12, 256>>>(offs, w4, b4);
    // grid*256 divisible by 24 -> grid divisible by 3.
    pln_norm_kernel<<<1185, 256>>>(x4, idx, out4);
}

// round 12
// speedup vs baseline: 1.0529x; 1.0529x over previous
#include <cuda_runtime.h>
#include <cuda_bf16.h>

// PointLayerNorm, R12: reduce runs as ONE 1024-thread CTA per SM (grid 148)
// to kill cross-CTA L1tex-queue spread (measured mode-W spread 1.003 vs
// mode-A 1.911). Norm reverted to the R10 body (93.6us measured; R11's
// unroll regressed it). Stats zeroing stays folded into finalize.

#define Bc 4
#define Nc 200000
#define Cc 96
#define C4 (Cc / 4)            // 24 float4 per point
#define Sc 32
#define KEYS (Bc * Sc)
#define EPSF 1e-5f
#define RGRID 148              // one 1024-thread CTA per SM
#define RTPB 1024

__device__ float g_sum[KEYS];    // static zero-init; re-zeroed by finalize
__device__ float g_sumsq[KEYS];
__device__ float4 g_sc[KEYS * C4];   // per (key, c4) scale
__device__ float4 g_sh[KEYS * C4];   // per (key, c4) shift

__device__ __forceinline__ void acc4(const float4 v, float& s, float& s2) {
    s += (v.x + v.y) + (v.z + v.w);
    s2 = fmaf(v.x, v.x, s2); s2 = fmaf(v.y, v.y, s2);
    s2 = fmaf(v.z, v.z, s2); s2 = fmaf(v.w, v.w, s2);
}

// Reduce: one warp owns a contiguous range of global points [g0, g1).
// Segment runs derived from the 33-entry offs array (batch_indices is
// non-decreasing) -> no idx loads, no shuffles/ballots in the hot loop.
__global__ __launch_bounds__(RTPB, 1) void pln_reduce_kernel(
    const float4* __restrict__ x4, const int* __restrict__ offs)
{
    const int P = Bc * Nc;
    int wid    = (blockIdx.x * blockDim.x + threadIdx.x) >> 5;
    int lane   = threadIdx.x & 31;
    int totalW = (RGRID * RTPB) >> 5;                        // 4736 warps
    int chunk  = (((P + totalW - 1) / totalW) + 15) & ~15;   // 176
    int g0 = wid * chunk;
    int g1 = min(g0 + chunk, P);
    if (g0 >= g1) return;

    int g = g0;
    while (g < g1) {
        int b = g / Nc;
        int n = g - b * Nc;
        int nlimit = min(Nc, n + (g1 - g));     // batch-local end of our range

        // binary search: largest seg with offs[seg] <= n  (offs[0]=0)
        int seg = 0;
        #pragma unroll
        for (int step = 16; step; step >>= 1) {
            int cand = seg + step;
            if (cand <= Sc - 1 && __ldg(&offs[cand]) <= n) seg = cand;
        }

        while (n < nlimit) {
            int rend = min(nlimit, __ldg(&offs[seg + 1]));
            int key  = b * Sc + seg;

            float sA = 0.f, sB = 0.f, s2A = 0.f, s2B = 0.f;
            const float4* base = x4 + ((size_t)b * Nc + n) * C4;

            // 16-point groups: 384 consecutive float4s, 12 LDG.128 per lane.
            for (; n + 16 <= rend; n += 16, base += 384) {
                float4 v0  = __ldg(base + lane);
                float4 v1  = __ldg(base + lane + 32);
                float4 v2  = __ldg(base + lane + 64);
                float4 v3  = __ldg(base + lane + 96);
                float4 v4  = __ldg(base + lane + 128);
                float4 v5  = __ldg(base + lane + 160);
                float4 v6  = __ldg(base + lane + 192);
                float4 v7  = __ldg(base + lane + 224);
                float4 v8  = __ldg(base + lane + 256);
                float4 v9  = __ldg(base + lane + 288);
                float4 v10 = __ldg(base + lane + 320);
                float4 v11 = __ldg(base + lane + 352);
                acc4(v0,  sA, s2A); acc4(v1,  sB, s2B);
                acc4(v2,  sA, s2A); acc4(v3,  sB, s2B);
                acc4(v4,  sA, s2A); acc4(v5,  sB, s2B);
                acc4(v6,  sA, s2A); acc4(v7,  sB, s2B);
                acc4(v8,  sA, s2A); acc4(v9,  sB, s2B);
                acc4(v10, sA, s2A); acc4(v11, sB, s2B);
            }
            // 8-point group (at most one)
            for (; n + 8 <= rend; n += 8, base += 192) {
                float4 v0 = __ldg(base + lane);
                float4 v1 = __ldg(base + lane + 32);
                float4 v2 = __ldg(base + lane + 64);
                float4 v3 = __ldg(base + lane + 96);
                float4 v4 = __ldg(base + lane + 128);
                float4 v5 = __ldg(base + lane + 160);
                acc4(v0, sA, s2A); acc4(v1, sB, s2B);
                acc4(v2, sA, s2A); acc4(v3, sB, s2B);
                acc4(v4, sA, s2A); acc4(v5, sB, s2B);
            }
            // remainder: single points, 24 active lanes
            for (; n < rend; ++n, base += 24) {
                if (lane < C4) {
                    float4 v = __ldg(base + lane);
                    acc4(v, sA, s2A);
                }
            }

            // flush this run
            float s = sA + sB, s2 = s2A + s2B;
            #pragma unroll
            for (int o = 16; o; o >>= 1) {
                s  += __shfl_xor_sync(0xffffffffu, s,  o);
                s2 += __shfl_xor_sync(0xffffffffu, s2, o);
            }
            if (lane == 0) {
                atomicAdd(&g_sum[key],   s);
                atomicAdd(&g_sumsq[key], s2);
            }
            if (n < nlimit) ++seg;   // next segment in this batch
        }
        g = b * Nc + nlimit;         // next batch-slice re-searches seg
    }
}

// Per-(key, c4) scale/shift tables, then zero the stats for the next replay.
__global__ void pln_finalize_kernel(const int* __restrict__ offs,
                                    const float4* __restrict__ w4,
                                    const float4* __restrict__ b4)
{
    int i = blockIdx.x * blockDim.x + threadIdx.x;
    if (i < KEYS * C4) {
        int k  = i / C4;
        int c4 = i - k * C4;
        int seg = k & (Sc - 1);
        float cnt = (float)(offs[seg + 1] - offs[seg]) * (float)Cc;
        float m   = g_sum[k] / cnt;
        float var = g_sumsq[k] / cnt - m * m;
        float iv  = rsqrtf(var + EPSF);
        float4 wv = __ldg(w4 + c4);
        float4 bv = __ldg(b4 + c4);
        float4 sc, sh;
        sc.x = iv * wv.x; sh.x = fmaf(-m, sc.x, bv.x);
        sc.y = iv * wv.y; sh.y = fmaf(-m, sc.y, bv.y);
        sc.z = iv * wv.z; sh.z = fmaf(-m, sc.z, bv.z);
        sc.w = iv * wv.w; sh.w = fmaf(-m, sc.w, bv.w);
        g_sc[i] = sc;
        g_sh[i] = sh;
        if (c4 == 0) {                // one thread per key zeroes its stats
            g_sum[k]   = 0.f;
            g_sumsq[k] = 0.f;
        }
    }
}

// Norm: exact R10 body (measured 93.6us, mixed-R/W DRAM ceiling).
__global__ __launch_bounds__(256) void pln_norm_kernel(
    const float4* __restrict__ x4, const int* __restrict__ idx,
    float4* __restrict__ out4)
{
    const int P = Bc * Nc;
    const int E = P * C4;                      // 19,200,000 float4s
    int T   = gridDim.x * blockDim.x;          // multiple of 24 by launch config
    int tid = blockIdx.x * blockDim.x + threadIdx.x;
    int dp  = T / C4;

    int p  = tid / C4;
    int c4 = tid - p * C4;
    int b  = p / Nc;
    int n  = p - b * Nc;

    for (int e = tid; e < E; e += T) {
        int key = (b * Sc + __ldg(&idx[n])) & (KEYS - 1);
        int t   = key * C4 + c4;
        float4 sc = g_sc[t];
        float4 sh = g_sh[t];
        float4 xv = __ldcs(x4 + e);
        float4 o;
        o.x = fmaf(xv.x, sc.x, sh.x);
        o.y = fmaf(xv.y, sc.y, sh.y);
        o.z = fmaf(xv.z, sc.z, sh.z);
        o.w = fmaf(xv.w, sc.w, sh.w);
        __stcs(out4 + e, o);
        n += dp;
        if (n >= Nc) { n -= Nc; ++b; }
    }
}

extern "C" void kernel_launch(void* const* d_in, const int* in_sizes, int n_in,
                              void* d_out, int out_size) {
    const float4* x4   = (const float4*)d_in[0];
    const int*    offs = (const int*)d_in[1];
    const int*    idx  = (const int*)d_in[2];
    const float4* w4   = (const float4*)d_in[3];
    const float4* b4   = (const float4*)d_in[4];
    float4* out4 = (float4*)d_out;

    pln_reduce_kernel<<<RGRID, RTPB>>>(x4, offs);
    pln_finalize_kernel<<<12, 256>>>(offs, w4, b4);
    // grid*256 divisible by 24 -> grid divisible by 3.
    pln_norm_kernel<<<1185, 256>>>(x4, idx, out4);
}